// round 8
// baseline (speedup 1.0000x reference)
#include <cuda_runtime.h>
#include <cstddef>

#define NJ 24

__device__ float g_partials[16384];
__device__ unsigned int g_count = 0;

// Fast inverse sqrt on the FMA pipe (avoids MUFU throughput bound).
__device__ __forceinline__ float rsq(float x) {
    float y = __int_as_float(0x5f3759dfu - (__float_as_uint(x) >> 1));
    float hx = 0.5f * x;
    y = y * (1.5f - hx * y * y);
    y = y * (1.5f - hx * y * y);
    return y;
}

__device__ __forceinline__ void cpasync16(unsigned int dst, const float4* src) {
    asm volatile("cp.async.cg.shared.global [%0], [%1], 16;" :: "r"(dst), "l"(src));
}
__device__ __forceinline__ void cp_commit() {
    asm volatile("cp.async.commit_group;" ::: "memory");
}
__device__ __forceinline__ void cp_wait1() {
    asm volatile("cp.async.wait_group 1;" ::: "memory");
}
__device__ __forceinline__ void cp_wait0() {
    asm volatile("cp.async.wait_group 0;" ::: "memory");
}

// Block: 128 threads = 4 warps. Warp w owns 16 frames, lane l -> frame
// (l>>1), pose (l&1). FK runs in 6 stages of 4 joints, double-buffered
// cp.async staging into warp-private smem (no block syncs in mainloop).
// Loss is folded INTO the FK loop: the A/B partner lane is at the same
// unrolled instruction, so shfl_xor(.,1) exchanges each end-effector
// coordinate as soon as it is produced (no ee[5][3] register array).
__global__ void __launch_bounds__(128, 6)
ee_loss_kernel(const float* __restrict__ poseA, const float* __restrict__ poseB,
               const float* __restrict__ offA,  const float* __restrict__ offB,
               const float* __restrict__ tA,    const float* __restrict__ tB,
               float* __restrict__ out,
               int F, int nb, float inv_count)
{
    constexpr int PARENTS[NJ] = {-1,0,0,0,1,2,3,4,5,6,7,8,9,9,9,12,13,14,16,17,18,19,20,21};
    constexpr bool IS_EE[NJ] = {false,false,false,false,false,false,false,false,false,false,
                                true, true, false,false,false,true, false,false,false,false,
                                false,false,true, true};
    constexpr int EE_SLOT[NJ] = {-1,-1,-1,-1,-1,-1,-1,-1,-1,-1,
                                  0, 1,-1,-1,-1, 2,-1,-1,-1,-1,
                                 -1,-1, 3, 4};
    constexpr int END_SITES[5] = {10,11,15,22,23};

    __shared__ float4 sm[4 * 640];          // 4 warps x 2 bufs x 320 f4 = 40 KB
    __shared__ float  s_iS[2][3];
    __shared__ float  s_c[2][15];
    __shared__ float  s_wsum[4];
    __shared__ bool   s_last;
    __shared__ double s_dsum[128];

    const int tid  = threadIdx.x;
    const int warp = tid >> 5;
    const int lane = tid & 31;

    if (tid == 0) {
        float mnA[3], mxA[3], mnB[3], mxB[3];
#pragma unroll
        for (int a = 0; a < 3; ++a) { mnA[a] = mxA[a] = tA[a]; mnB[a] = mxB[a] = tB[a]; }
#pragma unroll
        for (int j = 1; j < NJ; ++j) {
#pragma unroll
            for (int a = 0; a < 3; ++a) {
                const float va = tA[j * 3 + a];
                const float vb = tB[j * 3 + a];
                mnA[a] = fminf(mnA[a], va); mxA[a] = fmaxf(mxA[a], va);
                mnB[a] = fminf(mnB[a], vb); mxB[a] = fmaxf(mxB[a], vb);
            }
        }
#pragma unroll
        for (int a = 0; a < 3; ++a) {
            s_iS[0][a] = 1.0f / (mxA[a] - mnA[a]);
            s_iS[1][a] = 1.0f / (mxB[a] - mnB[a]);
        }
#pragma unroll
        for (int e = 0; e < 5; ++e) {
#pragma unroll
            for (int a = 0; a < 3; ++a) {
                s_c[0][e * 3 + a] = tA[END_SITES[e] * 3 + a] * s_iS[0][a];
                s_c[1][e * 3 + a] = tB[END_SITES[e] * 3 + a] * s_iS[1][a];
            }
        }
    }
    __syncthreads();       // once, before the (sync-free) mainloop

    const int fbase      = blockIdx.x * 64 + warp * 16;  // warp's first frame
    const int frameLocal = lane >> 1;
    const int frame      = fbase + frameLocal;
    const int pb         = lane & 1;
    const bool valid     = (frame < F);

    const float4* __restrict__ pvA = reinterpret_cast<const float4*>(poseA);
    const float4* __restrict__ pvB = reinterpret_cast<const float4*>(poseB);
    const float4* __restrict__ uvA = reinterpret_cast<const float4*>(offA);
    const float4* __restrict__ uvB = reinterpret_cast<const float4*>(offB);

    float4* const wb = sm + warp * 640;
    const unsigned int wb_u = (unsigned int)__cvta_generic_to_shared(wb);

    // Per-lane load descriptors (stage-independent).
    int pfr[3], pj[3];
#pragma unroll
    for (int m = 0; m < 3; ++m) { const int k = lane + 32 * m; pfr[m] = k / 6; pj[m] = k % 6; }
    int osel[3], ofr[3], oj[3];
#pragma unroll
    for (int m = 0; m < 3; ++m) {
        const int k = lane + 32 * m;
        osel[m] = k / 48;
        const int idx = k % 48;
        ofr[m] = idx / 3; oj[m] = idx % 3;
    }

    auto load_stage = [&](int st, int b) {
        const unsigned int bu = wb_u + (unsigned int)(b * 320 * 16);
#pragma unroll
        for (int m = 0; m < 3; ++m) {
            const int fr = min(fbase + pfr[m], F - 1);
            const size_t so = (size_t)fr * 36 + st * 6 + pj[m];
            const unsigned int d = (unsigned int)((pfr[m] * 7 + pj[m]) * 16);
            cpasync16(bu + d,            pvA + so);
            cpasync16(bu + d + 112 * 16, pvB + so);
        }
#pragma unroll
        for (int m = 0; m < 3; ++m) {
            const int fr = min(fbase + ofr[m], F - 1);
            const float4* src = (osel[m] ? uvB : uvA) + (size_t)fr * 18 + st * 3 + oj[m];
            cpasync16(bu + (unsigned int)((224 + osel[m] * 48 + ofr[m] * 3 + oj[m]) * 16), src);
        }
        cp_commit();
    };

    float O[NJ][9];
    float P[NJ][3];
    float s = 0.0f;

    load_stage(0, 0);

#pragma unroll
    for (int st = 0; st < 6; ++st) {
        const int b = st & 1;
        if (st < 5) { load_stage(st + 1, b ^ 1); cp_wait1(); }
        else        { cp_wait0(); }
        __syncwarp();

        const float4* myPose = wb + b * 320 + pb * 112 + frameLocal * 7;
        const float4* myOff  = wb + b * 320 + 224 + pb * 48 + frameLocal * 3;

        // FK runs on ALL lanes (clamped loads define the data); only the
        // accumulation is guarded by `valid`, keeping shfl lockstep legal.
        float4 q0, q1, q2, u0, u1, u2;
#pragma unroll
        for (int li = 0; li < 4; ++li) {
            const int i = st * 4 + li;

            if ((li & 1) == 0) {
                const int bb = (3 * li) / 2;
                q0 = myPose[bb]; q1 = myPose[bb + 1]; q2 = myPose[bb + 2];
            }
            float a0, a1, a2, a3, a4, a5;
            if ((li & 1) == 0) { a0 = q0.x; a1 = q0.y; a2 = q0.z; a3 = q0.w; a4 = q1.x; a5 = q1.y; }
            else               { a0 = q1.z; a1 = q1.w; a2 = q2.x; a3 = q2.y; a4 = q2.z; a5 = q2.w; }

            if (li == 0) { u0 = myOff[0]; u1 = myOff[1]; u2 = myOff[2]; }
            float ox, oy, oz;
            switch (li & 3) {
                case 0:  ox = u0.x; oy = u0.y; oz = u0.z; break;
                case 1:  ox = u0.w; oy = u1.x; oz = u1.y; break;
                case 2:  ox = u1.z; oy = u1.w; oz = u2.x; break;
                default: ox = u2.y; oy = u2.z; oz = u2.w; break;
            }

            float r0 = 0.f, r1 = 0.f, r2 = 0.f, r3 = 0.f, r4 = 0.f,
                  r5 = 0.f, r6 = 0.f, r7 = 0.f, r8 = 0.f;
            if (!IS_EE[i]) {
                const float n1 = a0 * a0 + a1 * a1 + a2 * a2;
                const float i1 = rsq(n1);
                r0 = a0 * i1; r1 = a1 * i1; r2 = a2 * i1;
                const float d  = r0 * a3 + r1 * a4 + r2 * a5;
                const float c0 = a3 - d * r0;
                const float c1 = a4 - d * r1;
                const float c2 = a5 - d * r2;
                const float n2 = c0 * c0 + c1 * c1 + c2 * c2;
                const float i2 = rsq(n2);
                r3 = c0 * i2; r4 = c1 * i2; r5 = c2 * i2;
                r6 = r1 * r5 - r2 * r4;
                r7 = r2 * r3 - r0 * r5;
                r8 = r0 * r4 - r1 * r3;
            }

            if (i == 0) {
                P[0][0] = ox; P[0][1] = oy; P[0][2] = oz;
                O[0][0] = r0; O[0][1] = r1; O[0][2] = r2;
                O[0][3] = r3; O[0][4] = r4; O[0][5] = r5;
                O[0][6] = r6; O[0][7] = r7; O[0][8] = r8;
            } else {
                const int p = PARENTS[i];
                const float px = O[p][0] * ox + O[p][1] * oy + O[p][2] * oz + P[p][0];
                const float py = O[p][3] * ox + O[p][4] * oy + O[p][5] * oz + P[p][1];
                const float pz = O[p][6] * ox + O[p][7] * oy + O[p][8] * oz + P[p][2];
                if (IS_EE[i]) {
                    // Immediate loss: exchange with partner lane (A<->B).
                    const int sl = EE_SLOT[i];
                    const float v0 = px * s_iS[pb][0] - s_c[pb][sl * 3 + 0];
                    const float v1 = py * s_iS[pb][1] - s_c[pb][sl * 3 + 1];
                    const float v2 = pz * s_iS[pb][2] - s_c[pb][sl * 3 + 2];
                    const float w0 = __shfl_xor_sync(0xFFFFFFFFu, v0, 1);
                    const float w1 = __shfl_xor_sync(0xFFFFFFFFu, v1, 1);
                    const float w2 = __shfl_xor_sync(0xFFFFFFFFu, v2, 1);
                    if (valid) {
                        const float d0 = v0 - w0, d1 = v1 - w1, d2 = v2 - w2;
                        s = fmaf(d0, d0, s);
                        s = fmaf(d1, d1, s);
                        s = fmaf(d2, d2, s);
                    }
                } else {
                    P[i][0] = px; P[i][1] = py; P[i][2] = pz;
                    O[i][0] = O[p][0] * r0 + O[p][1] * r3 + O[p][2] * r6;
                    O[i][1] = O[p][0] * r1 + O[p][1] * r4 + O[p][2] * r7;
                    O[i][2] = O[p][0] * r2 + O[p][1] * r5 + O[p][2] * r8;
                    O[i][3] = O[p][3] * r0 + O[p][4] * r3 + O[p][5] * r6;
                    O[i][4] = O[p][3] * r1 + O[p][4] * r4 + O[p][5] * r7;
                    O[i][5] = O[p][3] * r2 + O[p][4] * r5 + O[p][5] * r8;
                    O[i][6] = O[p][6] * r0 + O[p][7] * r3 + O[p][8] * r6;
                    O[i][7] = O[p][6] * r1 + O[p][7] * r4 + O[p][8] * r7;
                    O[i][8] = O[p][6] * r2 + O[p][7] * r5 + O[p][8] * r8;
                }
            }
        }
        __syncwarp();   // all lanes done reading buf b before it is reloaded
    }

    // deterministic in-block reduction
#pragma unroll
    for (int o = 16; o > 0; o >>= 1)
        s += __shfl_xor_sync(0xFFFFFFFFu, s, o);
    if (lane == 0) s_wsum[warp] = s;
    __syncthreads();

    if (tid == 0) {
        g_partials[blockIdx.x] = s_wsum[0] + s_wsum[1] + s_wsum[2] + s_wsum[3];
        __threadfence();
        const unsigned int done = atomicAdd(&g_count, 1u);
        s_last = (done == (unsigned int)(nb - 1));
    }
    __syncthreads();

    // Last block reduces all partials in a FIXED order -> deterministic.
    if (s_last) {
        double ds = 0.0;
        for (int i = tid; i < nb; i += 128)
            ds += (double)g_partials[i];
        s_dsum[tid] = ds;
        __syncthreads();
#pragma unroll
        for (int k = 64; k > 0; k >>= 1) {
            if (tid < k) s_dsum[tid] += s_dsum[tid + k];
            __syncthreads();
        }
        if (tid == 0) {
            out[0] = (float)(s_dsum[0] * (double)inv_count);
            g_count = 0;   // reset for next graph replay
        }
    }
}

extern "C" void kernel_launch(void* const* d_in, const int* in_sizes, int n_in,
                              void* d_out, int out_size)
{
    const float* poseA = (const float*)d_in[0];
    const float* poseB = (const float*)d_in[1];
    const float* offA  = (const float*)d_in[2];
    const float* offB  = (const float*)d_in[3];
    const float* tA    = (const float*)d_in[4];
    const float* tB    = (const float*)d_in[5];
    float* out = (float*)d_out;

    const int F = in_sizes[0] / (NJ * 6);
    const int framesPerBlock = 64;                 // 4 warps x 16 frames
    const int nb = (F + framesPerBlock - 1) / framesPerBlock;
    const float inv_count = 1.0f / ((float)F * 15.0f * 2.0f);

    ee_loss_kernel<<<nb, 128>>>(poseA, poseB, offA, offB, tA, tB, out, F, nb, inv_count);
}

// round 9
// speedup vs baseline: 1.1250x; 1.1250x over previous
#include <cuda_runtime.h>
#include <cstddef>

#define NJ 24

__device__ float g_partials[16384];
__device__ unsigned int g_count = 0;

// Fast inverse sqrt on the FMA pipe (avoids MUFU throughput bound).
__device__ __forceinline__ float rsq(float x) {
    float y = __int_as_float(0x5f3759dfu - (__float_as_uint(x) >> 1));
    float hx = 0.5f * x;
    y = y * (1.5f - hx * y * y);
    y = y * (1.5f - hx * y * y);
    return y;
}

// Forward kinematics for one frame of one pose; emits the 5 end-site positions.
// poseF: 144 floats (24 x 6), offF: 72 floats (24 x 3). Both 16B-aligned.
// Plain float4 loads (default caching): each 128B line is reused ~4.5x by the
// rolling q0/q1/q2 window out of L1 — do NOT use evict-first (.cs) here.
__device__ __forceinline__ void fk_ee(const float* __restrict__ poseF,
                                      const float* __restrict__ offF,
                                      float ee[5][3])
{
    constexpr int PARENTS[NJ] = {-1,0,0,0,1,2,3,4,5,6,7,8,9,9,9,12,13,14,16,17,18,19,20,21};
    constexpr bool IS_EE[NJ] = {false,false,false,false,false,false,false,false,false,false,
                                true, true, false,false,false,true, false,false,false,false,
                                false,false,true, true};
    constexpr int EE_SLOT[NJ] = {-1,-1,-1,-1,-1,-1,-1,-1,-1,-1,
                                  0, 1,-1,-1,-1, 2,-1,-1,-1,-1,
                                 -1,-1, 3, 4};

    float O[NJ][9];   // global orientations (row-major); scalarized by full unroll
    float P[NJ][3];   // global positions
    const float4* __restrict__ pv = reinterpret_cast<const float4*>(poseF);
    const float4* __restrict__ uv = reinterpret_cast<const float4*>(offF);
    float4 q0, q1, q2;   // rolling pose window (12 floats = 2 joints)
    float4 u0, u1, u2;   // rolling offset window (12 floats = 4 joints)

#pragma unroll
    for (int i = 0; i < NJ; ++i) {
        if ((i & 1) == 0) {
            const int b = (3 * i) / 2;          // float4 index of pose float 6*i
            q0 = pv[b]; q1 = pv[b + 1]; q2 = pv[b + 2];
        }
        float a0, a1, a2, a3, a4, a5;
        if ((i & 1) == 0) { a0 = q0.x; a1 = q0.y; a2 = q0.z; a3 = q0.w; a4 = q1.x; a5 = q1.y; }
        else              { a0 = q1.z; a1 = q1.w; a2 = q2.x; a3 = q2.y; a4 = q2.z; a5 = q2.w; }

        if ((i & 3) == 0) {
            const int b = (3 * i) / 4;          // float4 index of offset float 3*i
            u0 = uv[b]; u1 = uv[b + 1]; u2 = uv[b + 2];
        }
        float ox, oy, oz;
        switch (i & 3) {
            case 0:  ox = u0.x; oy = u0.y; oz = u0.z; break;
            case 1:  ox = u0.w; oy = u1.x; oz = u1.y; break;
            case 2:  ox = u1.z; oy = u1.w; oz = u2.x; break;
            default: ox = u2.y; oy = u2.z; oz = u2.w; break;
        }

        // 6D -> rotation matrix (rows b1,b2,b3). Skipped for leaf end-sites.
        float r0 = 0.f, r1 = 0.f, r2 = 0.f, r3 = 0.f, r4 = 0.f,
              r5 = 0.f, r6 = 0.f, r7 = 0.f, r8 = 0.f;
        if (!IS_EE[i]) {
            const float n1 = a0 * a0 + a1 * a1 + a2 * a2;
            const float i1 = rsq(n1);
            r0 = a0 * i1; r1 = a1 * i1; r2 = a2 * i1;
            const float d  = r0 * a3 + r1 * a4 + r2 * a5;
            const float c0 = a3 - d * r0;
            const float c1 = a4 - d * r1;
            const float c2 = a5 - d * r2;
            const float n2 = c0 * c0 + c1 * c1 + c2 * c2;
            const float i2 = rsq(n2);
            r3 = c0 * i2; r4 = c1 * i2; r5 = c2 * i2;
            r6 = r1 * r5 - r2 * r4;
            r7 = r2 * r3 - r0 * r5;
            r8 = r0 * r4 - r1 * r3;
        }

        if (i == 0) {
            P[0][0] = ox; P[0][1] = oy; P[0][2] = oz;
            O[0][0] = r0; O[0][1] = r1; O[0][2] = r2;
            O[0][3] = r3; O[0][4] = r4; O[0][5] = r5;
            O[0][6] = r6; O[0][7] = r7; O[0][8] = r8;
        } else {
            const int p = PARENTS[i];
            const float px = O[p][0] * ox + O[p][1] * oy + O[p][2] * oz + P[p][0];
            const float py = O[p][3] * ox + O[p][4] * oy + O[p][5] * oz + P[p][1];
            const float pz = O[p][6] * ox + O[p][7] * oy + O[p][8] * oz + P[p][2];
            if (IS_EE[i]) {
                const int s = EE_SLOT[i];
                ee[s][0] = px; ee[s][1] = py; ee[s][2] = pz;
            } else {
                P[i][0] = px; P[i][1] = py; P[i][2] = pz;
                // O[i] = O[p] @ R
                O[i][0] = O[p][0] * r0 + O[p][1] * r3 + O[p][2] * r6;
                O[i][1] = O[p][0] * r1 + O[p][1] * r4 + O[p][2] * r7;
                O[i][2] = O[p][0] * r2 + O[p][1] * r5 + O[p][2] * r8;
                O[i][3] = O[p][3] * r0 + O[p][4] * r3 + O[p][5] * r6;
                O[i][4] = O[p][3] * r1 + O[p][4] * r4 + O[p][5] * r7;
                O[i][5] = O[p][3] * r2 + O[p][4] * r5 + O[p][5] * r8;
                O[i][6] = O[p][6] * r0 + O[p][7] * r3 + O[p][8] * r6;
                O[i][7] = O[p][6] * r1 + O[p][7] * r4 + O[p][8] * r7;
                O[i][8] = O[p][6] * r2 + O[p][7] * r5 + O[p][8] * r8;
            }
        }
    }
}

__global__ void __launch_bounds__(128)
ee_loss_kernel(const float* __restrict__ poseA, const float* __restrict__ poseB,
               const float* __restrict__ offA,  const float* __restrict__ offB,
               const float* __restrict__ tA,    const float* __restrict__ tB,
               float* __restrict__ out,
               int F, int nb, float inv_count)
{
    constexpr int END_SITES[5] = {10,11,15,22,23};
    __shared__ float s_iSA[3], s_iSB[3], s_c[15];   // c = tEA*iSA - tEB*iSB
    __shared__ float s_wsum[4];
    __shared__ bool  s_last;
    __shared__ double s_dsum[128];

    if (threadIdx.x == 0) {
        float mnA[3], mxA[3], mnB[3], mxB[3];
#pragma unroll
        for (int a = 0; a < 3; ++a) {
            mnA[a] = mxA[a] = tA[a];
            mnB[a] = mxB[a] = tB[a];
        }
#pragma unroll
        for (int j = 1; j < NJ; ++j) {
#pragma unroll
            for (int a = 0; a < 3; ++a) {
                const float va = tA[j * 3 + a];
                const float vb = tB[j * 3 + a];
                mnA[a] = fminf(mnA[a], va); mxA[a] = fmaxf(mxA[a], va);
                mnB[a] = fminf(mnB[a], vb); mxB[a] = fmaxf(mxB[a], vb);
            }
        }
        float iSA[3], iSB[3];
#pragma unroll
        for (int a = 0; a < 3; ++a) {
            iSA[a] = 1.0f / (mxA[a] - mnA[a]);
            iSB[a] = 1.0f / (mxB[a] - mnB[a]);
            s_iSA[a] = iSA[a];
            s_iSB[a] = iSB[a];
        }
#pragma unroll
        for (int e = 0; e < 5; ++e) {
#pragma unroll
            for (int a = 0; a < 3; ++a) {
                s_c[e * 3 + a] = tA[END_SITES[e] * 3 + a] * iSA[a]
                               - tB[END_SITES[e] * 3 + a] * iSB[a];
            }
        }
    }
    __syncthreads();

    const int frame = blockIdx.x * blockDim.x + threadIdx.x;
    float s = 0.0f;
    if (frame < F) {
        float eeA[5][3], eeB[5][3];
        fk_ee(poseA + (size_t)frame * 144, offA + (size_t)frame * 72, eeA);
        fk_ee(poseB + (size_t)frame * 144, offB + (size_t)frame * 72, eeB);
#pragma unroll
        for (int e = 0; e < 5; ++e) {
#pragma unroll
            for (int a = 0; a < 3; ++a) {
                const float d = eeA[e][a] * s_iSA[a]
                              - eeB[e][a] * s_iSB[a]
                              - s_c[e * 3 + a];
                s = fmaf(d, d, s);
            }
        }
    }

    // deterministic in-block reduction
#pragma unroll
    for (int o = 16; o > 0; o >>= 1)
        s += __shfl_xor_sync(0xFFFFFFFFu, s, o);
    const int wid  = threadIdx.x >> 5;
    const int lane = threadIdx.x & 31;
    if (lane == 0) s_wsum[wid] = s;
    __syncthreads();

    if (threadIdx.x == 0) {
        g_partials[blockIdx.x] = s_wsum[0] + s_wsum[1] + s_wsum[2] + s_wsum[3];
        __threadfence();
        const unsigned int done = atomicAdd(&g_count, 1u);
        s_last = (done == (unsigned int)(nb - 1));
    }
    __syncthreads();

    // Last block to finish reduces all partials in a FIXED order
    // (independent of which block it is) -> deterministic; writes d_out
    // directly so the graph has a single kernel node.
    if (s_last) {
        double ds = 0.0;
        for (int i = threadIdx.x; i < nb; i += 128)
            ds += (double)g_partials[i];
        s_dsum[threadIdx.x] = ds;
        __syncthreads();
#pragma unroll
        for (int k = 64; k > 0; k >>= 1) {
            if (threadIdx.x < k) s_dsum[threadIdx.x] += s_dsum[threadIdx.x + k];
            __syncthreads();
        }
        if (threadIdx.x == 0) {
            out[0] = (float)(s_dsum[0] * (double)inv_count);
            g_count = 0;   // reset for the next graph replay
        }
    }
}

extern "C" void kernel_launch(void* const* d_in, const int* in_sizes, int n_in,
                              void* d_out, int out_size)
{
    const float* poseA = (const float*)d_in[0];
    const float* poseB = (const float*)d_in[1];
    const float* offA  = (const float*)d_in[2];
    const float* offB  = (const float*)d_in[3];
    const float* tA    = (const float*)d_in[4];
    const float* tB    = (const float*)d_in[5];
    float* out = (float*)d_out;

    const int F = in_sizes[0] / (NJ * 6);
    const int threads = 128;
    const int nb = (F + threads - 1) / threads;
    const float inv_count = 1.0f / ((float)F * 15.0f);

    ee_loss_kernel<<<nb, threads>>>(poseA, poseB, offA, offB, tA, tB, out, F, nb, inv_count);
}